// round 15
// baseline (speedup 1.0000x reference)
#include <cuda_runtime.h>
#include <cuda_bf16.h>
#include <mma.h>
#include <math.h>
#include <stdint.h>

using namespace nvcuda;

#define L      4096
#define DM     768
#define DI     1536
#define DS     16
#define DTR    48
#define NCHUNK 64
#define CHUNK  (L / NCHUNK)          // 64
#define KPST   (2 * DM)              // storage: [ah|al] / [bh|bl]
#define G1_NCH 72                    // 72 chunks of 32 = 3 x 768 compute-K
#define KS2    6
#define KC2    (DI / KS2)
#define TSKIP  20.0f                 // exp(-20) ~ 2e-9: negligible vs 1e-3 gate

// ---------------- scratch ----------------
__device__ float g_xc_pre[L * DI];
__device__ float g_xc[L * DI];
__device__ float g_dt[L * DI];
__device__ float g_xdbl[L * 64];
__device__ float g_xdbl_part[KS2][L * 64];
__device__ float g_csum[NCHUNK * DI];
__device__ float g_csuf[NCHUNK * DI];
__device__ float g_hpart[NCHUNK * DI * DS];
__device__ float g_C[DS];
__device__ float g_z[DI];
__device__ float g_y[DI];
__device__ float g_outraw[DM];
__device__ int   g_nexp[DI * DS];
__device__ float g_fexp[DI * DS];
__device__ int   g_fast = 1;
__device__ __nv_bfloat16 g_feS[L * KPST];    // [ah | al]
__device__ __nv_bfloat16 g_wS[DI * KPST];    // [bh | bl]

__device__ __forceinline__ uint32_t smem_u32(const void* p) {
    uint32_t a;
    asm("{ .reg .u64 t; cvta.to.shared.u64 t, %1; cvt.u32.u64 %0, t; }" : "=r"(a) : "l"(p));
    return a;
}

// chunk t -> source K offsets: g0 ah*bh, g1 ah*bl, g2 al*bh
__device__ __forceinline__ void g1_koff(int t, int& ka, int& kb) {
    int g = t / 24, r = t - g * 24;
    int k = r * 32;
    ka = (g == 2) ? DM + k : k;
    kb = (g == 1) ? DM + k : k;
}

// ---------------- prep ----------------
__global__ void k_prep(const float* __restrict__ alog) {
    int i = blockIdx.x * blockDim.x + threadIdx.x;
    if (i >= DI * DS) return;
    int s = i % DS;
    float a = expf(alog[i]);
    int   n = (int)rintf(a);
    float f;
    bool isint = (n >= 0) && (fabsf(a - (float)n) <= 1e-4f * fmaxf(1.f, a));
    if (isint) { f = 0.f; }
    else { n = (int)floorf(a); f = a - (float)n; if (n < 0) { n = 0; f = a; } }
    g_nexp[i] = n;
    g_fexp[i] = f;
    if (!(isint && n == s + 1)) atomicAnd(&g_fast, 0);
}

// ---------------- fused split conversions (compact layout) ----------------
__global__ void k_cvt(const float* __restrict__ fe, const float* __restrict__ inw) {
    int i = blockIdx.x * blockDim.x + threadIdx.x;
    if (i < L * DM) {
        float x = fe[i];
        __nv_bfloat16 h = __float2bfloat16(x);
        __nv_bfloat16 lo = __float2bfloat16(x - __bfloat162float(h));
        int row = i / DM, col = i % DM;
        size_t base = (size_t)row * KPST;
        g_feS[base + col]      = h;
        g_feS[base + DM + col] = lo;
    } else {
        int j = i - L * DM;
        if (j >= DI * DM) return;
        float x = inw[j];
        __nv_bfloat16 h = __float2bfloat16(x);
        __nv_bfloat16 lo = __float2bfloat16(x - __bfloat162float(h));
        int row = j / DM, col = j % DM;
        size_t base = (size_t)row * KPST;
        g_wS[base + col]      = h;
        g_wS[base + DM + col] = lo;
    }
}

// ---------------- WMMA GEMM1 (R9 config), compact-layout chunk mapping ----
#define G1_BK 32
#define G1_LD 40
#define G1_STAGE_B (128 * G1_LD * 2)
#define G1_SMEM (6 * G1_STAGE_B)     // 61440

__global__ void __launch_bounds__(256)
k_gemm1_wmma() {
    extern __shared__ __align__(16) char dsm[];
    __nv_bfloat16 (*sA)[128][G1_LD] = reinterpret_cast<__nv_bfloat16 (*)[128][G1_LD]>(dsm);
    __nv_bfloat16 (*sB)[128][G1_LD] = reinterpret_cast<__nv_bfloat16 (*)[128][G1_LD]>(dsm + 3 * G1_STAGE_B);
    const int tid = threadIdx.x;
    const int wid = tid >> 5;
    const int wm = wid & 3;
    const int wn = wid >> 2;
    const int m0 = blockIdx.y * 128;
    const int n0 = blockIdx.x * 128;

    wmma::fragment<wmma::accumulator, 16, 16, 16, float> acc[2][4];
#pragma unroll
    for (int i = 0; i < 2; i++)
#pragma unroll
        for (int j = 0; j < 4; j++) wmma::fill_fragment(acc[i][j], 0.f);

    const int r0 = tid >> 2;
    const int c0 = (tid & 3) << 3;

#define G1_ISSUE(st, tt)                                                              \
    do {                                                                              \
        int _ka, _kb; g1_koff((tt), _ka, _kb);                                        \
        _Pragma("unroll")                                                             \
        for (int h = 0; h < 2; h++) {                                                 \
            int r = r0 + h * 64;                                                      \
            uint32_t sa = smem_u32(&sA[st][r][c0]);                                   \
            uint32_t sb = smem_u32(&sB[st][r][c0]);                                   \
            const void* ga = &g_feS[(size_t)(m0 + r) * KPST + _ka + c0];              \
            const void* gb = &g_wS[(size_t)(n0 + r) * KPST + _kb + c0];               \
            asm volatile("cp.async.cg.shared.global [%0], [%1], 16;" :: "r"(sa), "l"(ga)); \
            asm volatile("cp.async.cg.shared.global [%0], [%1], 16;" :: "r"(sb), "l"(gb)); \
        }                                                                             \
        asm volatile("cp.async.commit_group;");                                       \
    } while (0)

    G1_ISSUE(0, 0);
    G1_ISSUE(1, 1);
    for (int t = 0; t < G1_NCH; t++) {
        if (t + 1 < G1_NCH) asm volatile("cp.async.wait_group 1;");
        else                asm volatile("cp.async.wait_group 0;");
        __syncthreads();
        if (t + 2 < G1_NCH) G1_ISSUE((t + 2) % 3, t + 2);
        const int st = t % 3;
#pragma unroll
        for (int kk = 0; kk < G1_BK; kk += 16) {
            wmma::fragment<wmma::matrix_a, 16, 16, 16, __nv_bfloat16, wmma::row_major> fa[2];
            wmma::fragment<wmma::matrix_b, 16, 16, 16, __nv_bfloat16, wmma::col_major> fb[4];
#pragma unroll
            for (int i = 0; i < 2; i++)
                wmma::load_matrix_sync(fa[i], &sA[st][wm * 32 + i * 16][kk], G1_LD);
#pragma unroll
            for (int j = 0; j < 4; j++)
                wmma::load_matrix_sync(fb[j], &sB[st][wn * 64 + j * 16][kk], G1_LD);
#pragma unroll
            for (int i = 0; i < 2; i++)
#pragma unroll
                for (int j = 0; j < 4; j++)
                    wmma::mma_sync(acc[i][j], fa[i], fb[j], acc[i][j]);
        }
    }
    __syncthreads();
#pragma unroll
    for (int i = 0; i < 2; i++)
#pragma unroll
        for (int j = 0; j < 4; j++)
            wmma::store_matrix_sync(
                &g_xc_pre[(size_t)(m0 + wm * 32 + i * 16) * DI + n0 + wn * 64 + j * 16],
                acc[i][j], DI, wmma::mem_row_major);
}

// ------- SIMT SGEMM body (NT); EPI: 0=store, 1=softplus+chunksum ----------
template<int BM, int BN, int BK, int TM, int TN, int EPI>
__device__ __forceinline__ void sgemm_nt_body(
        int kbeg, int kend,
        const float* __restrict__ A, int lda,
        const float* __restrict__ B, int ldb,
        float* __restrict__ C, int ldc,
        const float* __restrict__ bias,
        int m0, int n0) {
    constexpr int THREADS = (BM / TM) * (BN / TN);
    __shared__ float As[BK][BM];
    __shared__ float Bs[BK][BN];
    const int tid = threadIdx.x;
    const int tx = tid % (BN / TN);
    const int ty = tid / (BN / TN);

    float acc[TM][TN];
#pragma unroll
    for (int i = 0; i < TM; i++)
#pragma unroll
        for (int j = 0; j < TN; j++) acc[i][j] = 0.f;

    for (int k0 = kbeg; k0 < kend; k0 += BK) {
#pragma unroll
        for (int i = tid; i < BM * (BK / 4); i += THREADS) {
            int r = i / (BK / 4), c = (i % (BK / 4)) * 4;
            float4 v = *reinterpret_cast<const float4*>(A + (size_t)(m0 + r) * lda + k0 + c);
            As[c + 0][r] = v.x; As[c + 1][r] = v.y; As[c + 2][r] = v.z; As[c + 3][r] = v.w;
        }
#pragma unroll
        for (int i = tid; i < BN * (BK / 4); i += THREADS) {
            int r = i / (BK / 4), c = (i % (BK / 4)) * 4;
            float4 v = *reinterpret_cast<const float4*>(B + (size_t)(n0 + r) * ldb + k0 + c);
            Bs[c + 0][r] = v.x; Bs[c + 1][r] = v.y; Bs[c + 2][r] = v.z; Bs[c + 3][r] = v.w;
        }
        __syncthreads();
#pragma unroll
        for (int kk = 0; kk < BK; kk++) {
            float ra[TM], rb[TN];
#pragma unroll
            for (int i = 0; i < TM; i += 4) {
                float4 v = *reinterpret_cast<const float4*>(&As[kk][ty * TM + i]);
                ra[i] = v.x; ra[i + 1] = v.y; ra[i + 2] = v.z; ra[i + 3] = v.w;
            }
#pragma unroll
            for (int j = 0; j < TN; j += 4) {
                float4 v = *reinterpret_cast<const float4*>(&Bs[kk][tx * TN + j]);
                rb[j] = v.x; rb[j + 1] = v.y; rb[j + 2] = v.z; rb[j + 3] = v.w;
            }
#pragma unroll
            for (int i = 0; i < TM; i++)
#pragma unroll
                for (int j = 0; j < TN; j++) acc[i][j] = fmaf(ra[i], rb[j], acc[i][j]);
        }
        __syncthreads();
    }

    if (EPI == 0) {
#pragma unroll
        for (int i = 0; i < TM; i++) {
#pragma unroll
            for (int j = 0; j < TN; j += 4) {
                float4 v = make_float4(acc[i][j], acc[i][j + 1], acc[i][j + 2], acc[i][j + 3]);
                *reinterpret_cast<float4*>(C + (size_t)(m0 + ty * TM + i) * ldc + n0 + tx * TN + j) = v;
            }
        }
    } else {
        __shared__ float s_cs[16][128];
        float colsum[TN];
#pragma unroll
        for (int j = 0; j < TN; j++) colsum[j] = 0.f;
#pragma unroll
        for (int i = 0; i < TM; i++) {
#pragma unroll
            for (int j = 0; j < TN; j += 4) {
                float vv[4];
                int col = n0 + tx * TN + j;
#pragma unroll
                for (int t = 0; t < 4; t++) {
                    float x = acc[i][j + t] + bias[col + t];
                    vv[t] = fmaxf(x, 0.f) + log1pf(__expf(-fabsf(x)));
                    colsum[j + t] += vv[t];
                }
                float4 v = make_float4(vv[0], vv[1], vv[2], vv[3]);
                *reinterpret_cast<float4*>(C + (size_t)(m0 + ty * TM + i) * ldc + n0 + tx * TN + j) = v;
            }
        }
#pragma unroll
        for (int j = 0; j < TN; j++) s_cs[ty][tx * TN + j] = colsum[j];
        __syncthreads();
        int h = tid >> 7, col = tid & 127;
        float s = 0.f;
#pragma unroll
        for (int q = 0; q < 8; q++) s += s_cs[h * 8 + q][col];
        g_csum[(size_t)(blockIdx.y * 2 + h) * DI + n0 + col] = s;
    }
}

__global__ void __launch_bounds__(256)
k_gemm2(const float* __restrict__ xpw) {
    int ck = blockIdx.x;
    sgemm_nt_body<64, 64, 16, 4, 4, 0>(
        ck * KC2, (ck + 1) * KC2,
        g_xc, DI, xpw, DI, g_xdbl_part[ck], 64, nullptr,
        blockIdx.y * 64, 0);
}

__global__ void k_xdblred() {
    int i = blockIdx.x * blockDim.x + threadIdx.x;
    if (i >= L * 64) return;
    float s = 0.f;
#pragma unroll
    for (int c = 0; c < KS2; c++) s += g_xdbl_part[c][i];
    g_xdbl[i] = s;
}

__global__ void __launch_bounds__(256)
k_gemm3(const float* __restrict__ dtw, const float* __restrict__ dtb) {
    sgemm_nt_body<128, 128, 16, 8, 8, 1>(
        0, DTR, g_xdbl, 64, dtw, DTR, g_dt, DI, dtb,
        blockIdx.y * 128, blockIdx.x * 128);
}

// ---------------- depthwise causal conv(4) + bias + silu (4d x 4l tiles) ---
__global__ void k_conv(const float* __restrict__ w, const float* __restrict__ b) {
    int idx = blockIdx.x * blockDim.x + threadIdx.x;
    if (idx >= (L / 4) * (DI / 4)) return;
    int dq = idx % (DI / 4);
    int g  = idx / (DI / 4);
    int d0 = dq * 4, l0 = g * 4;
    const float4* wp = reinterpret_cast<const float4*>(w) + d0;
    float4 w0 = wp[0], w1 = wp[1], w2 = wp[2], w3 = wp[3];
    float4 bb = *reinterpret_cast<const float4*>(b + d0);
    float4 x[7];
#pragma unroll
    for (int t = 0; t < 7; t++) {
        int l = l0 - 3 + t;
        x[t] = (l >= 0) ? *reinterpret_cast<const float4*>(&g_xc_pre[(size_t)l * DI + d0])
                        : make_float4(0.f, 0.f, 0.f, 0.f);
    }
#pragma unroll
    for (int t = 0; t < 4; t++) {
        float4 s;
        s.x = bb.x; s.y = bb.y; s.z = bb.z; s.w = bb.w;
        s.x = fmaf(w0.x, x[t].x, s.x); s.x = fmaf(w0.y, x[t+1].x, s.x); s.x = fmaf(w0.z, x[t+2].x, s.x); s.x = fmaf(w0.w, x[t+3].x, s.x);
        s.y = fmaf(w1.x, x[t].y, s.y); s.y = fmaf(w1.y, x[t+1].y, s.y); s.y = fmaf(w1.z, x[t+2].y, s.y); s.y = fmaf(w1.w, x[t+3].y, s.y);
        s.z = fmaf(w2.x, x[t].z, s.z); s.z = fmaf(w2.y, x[t+1].z, s.z); s.z = fmaf(w2.z, x[t+2].z, s.z); s.z = fmaf(w2.w, x[t+3].z, s.z);
        s.w = fmaf(w3.x, x[t].w, s.w); s.w = fmaf(w3.y, x[t+1].w, s.w); s.w = fmaf(w3.z, x[t+2].w, s.w); s.w = fmaf(w3.w, x[t+3].w, s.w);
        s.x = s.x / (1.f + __expf(-s.x));
        s.y = s.y / (1.f + __expf(-s.y));
        s.z = s.z / (1.f + __expf(-s.z));
        s.w = s.w / (1.f + __expf(-s.w));
        *reinterpret_cast<float4*>(&g_xc[(size_t)(l0 + t) * DI + d0]) = s;
    }
}

// ---------------- suffix over chunk sums ----------------
__global__ void k_chunksuf() {
    int d = blockIdx.x * blockDim.x + threadIdx.x;
    if (d >= DI) return;
    double t = 0.0;
    for (int c = NCHUNK - 1; c >= 0; --c) {
        g_csuf[c * DI + d] = (float)t;
        t += (double)g_csum[c * DI + d];
    }
}

// -------- parallel closed-form scan (B smem-staged, decay early-exit) ------
__global__ void k_scan() {
    __shared__ float sB[16][16];
    int tid = threadIdx.x;
    int d = blockIdx.x * 128 + tid;
    int c = blockIdx.y;
    float t = g_csuf[c * DI + d];
    float acc[DS];
#pragma unroll
    for (int s = 0; s < DS; s++) acc[s] = 0.f;
    const int l0 = c * CHUNK;
    const bool fast = (g_fast != 0);
    const bool sk = (t > TSKIP);              // whole chunk decays to zero

    if (__syncthreads_and(sk)) {
#pragma unroll
        for (int s = 0; s < DS; s++)
            g_hpart[(size_t)c * DI * DS + d * DS + s] = 0.f;
        return;
    }

    if (fast) {
        const bool wskip = __all_sync(0xFFFFFFFFu, sk);
        for (int lt = CHUNK - 16; lt >= 0; lt -= 16) {
            __syncthreads();
            {
                int i = tid * 2;
                int ll = i >> 4, ss = i & 15;
                float2 v = *reinterpret_cast<const float2*>(
                    &g_xdbl[(size_t)(l0 + lt + ll) * 64 + DTR + ss]);
                sB[ll][ss] = v.x; sB[ll][ss + 1] = v.y;
            }
            __syncthreads();
            if (!wskip) {
#pragma unroll
                for (int j = 15; j >= 0; --j) {
                    int l = l0 + lt + j;
                    float dt = g_dt[(size_t)l * DI + d];
                    float w  = dt * g_xc[(size_t)l * DI + d];
                    float E = __expf(-t);
                    float p = 1.f;
#pragma unroll
                    for (int s = 0; s < DS; s++) { p *= E; acc[s] = fmaf(w * p, sB[j][s], acc[s]); }
                    t += dt;
                }
            }
        }
    } else {
        if (!sk) {
            int nn[DS]; float ff[DS];
#pragma unroll
            for (int s = 0; s < DS; s++) { nn[s] = g_nexp[d * DS + s]; ff[s] = g_fexp[d * DS + s]; }
            for (int l = l0 + CHUNK - 1; l >= l0; --l) {
                const float* brow = g_xdbl + (size_t)l * 64 + DTR;
                float dt = g_dt[(size_t)l * DI + d];
                float w  = dt * g_xc[(size_t)l * DI + d];
                float E = __expf(-t);
#pragma unroll
                for (int s = 0; s < DS; s++) {
                    float p = 1.f, base = E;
                    int m = nn[s];
                    while (m) { if (m & 1) p *= base; base *= base; m >>= 1; }
                    if (ff[s] != 0.f) p *= __expf(-t * ff[s]);
                    acc[s] = fmaf(w * p, brow[s], acc[s]);
                }
                t += dt;
            }
        }
    }
#pragma unroll
    for (int s = 0; s < DS; s++)
        g_hpart[(size_t)c * DI * DS + d * DS + s] = acc[s];
}

// ---------------- fused last-step GEMVs (z and C) ----------------
__global__ void k_zc(const float* __restrict__ fe, const float* __restrict__ inw,
                     const float* __restrict__ xpw) {
    int gw = (blockIdx.x * blockDim.x + threadIdx.x) / 32;
    int lane = threadIdx.x % 32;
    if (gw < DI) {
        const float* a = fe + (size_t)(L - 1) * DM;
        const float* w = inw + (size_t)(DI + gw) * DM;
        float s = 0.f;
        for (int m = lane; m < DM; m += 32) s = fmaf(a[m], w[m], s);
#pragma unroll
        for (int o = 16; o; o >>= 1) s += __shfl_xor_sync(0xFFFFFFFFu, s, o);
        if (lane == 0) g_z[gw] = s;
    } else if (gw < DI + DS) {
        int sidx = gw - DI;
        const float* a = g_xc + (size_t)(L - 1) * DI;
        const float* w = xpw + (size_t)(DTR + DS + sidx) * DI;
        float acc = 0.f;
        for (int d = lane; d < DI; d += 32) acc = fmaf(a[d], w[d], acc);
#pragma unroll
        for (int o = 16; o; o >>= 1) acc += __shfl_xor_sync(0xFFFFFFFFu, acc, o);
        if (lane == 0) g_C[sidx] = acc;
    }
}

// ---------------- fused h-reduction + gated y ----------------
__global__ void k_hy(const float* __restrict__ Dp) {
    int d = blockIdx.x * blockDim.x + threadIdx.x;
    if (d >= DI) return;
    float h[DS];
#pragma unroll
    for (int s = 0; s < DS; s++) h[s] = 0.f;
    for (int c = 0; c < NCHUNK; c++) {
        const float4* hp = reinterpret_cast<const float4*>(&g_hpart[(size_t)c * DI * DS + d * DS]);
#pragma unroll
        for (int q = 0; q < 4; q++) {
            float4 v = hp[q];
            h[4 * q + 0] += v.x; h[4 * q + 1] += v.y;
            h[4 * q + 2] += v.z; h[4 * q + 3] += v.w;
        }
    }
    float s = 0.f;
#pragma unroll
    for (int j = 0; j < DS; j++) s = fmaf(h[j], g_C[j], s);
    float y = s + g_xc[(size_t)(L - 1) * DI + d] * Dp[d];
    float z = g_z[d];
    y *= z / (1.f + __expf(-z));
    g_y[d] = y;
}

__global__ void k_out1(const float* __restrict__ outw) {
    int e = blockIdx.x;
    const float* w = outw + (size_t)e * DI;
    float s = 0.f;
    for (int d = threadIdx.x; d < DI; d += 256) s = fmaf(g_y[d], w[d], s);
    __shared__ float red[256];
    red[threadIdx.x] = s;
    __syncthreads();
    for (int o = 128; o >= 1; o >>= 1) {
        if (threadIdx.x < o) red[threadIdx.x] += red[threadIdx.x + o];
        __syncthreads();
    }
    if (threadIdx.x == 0) g_outraw[e] = red[0];
}

__global__ void k_out2(float* __restrict__ out) {
    int t = threadIdx.x;
    float v = g_outraw[t];
    __shared__ float red[768];
    red[t] = v * v;
    __syncthreads();
    if (t < 256) red[t] += red[t + 256] + red[t + 512];
    __syncthreads();
    for (int o = 128; o >= 1; o >>= 1) {
        if (t < o) red[t] += red[t + o];
        __syncthreads();
    }
    float denom = fmaxf(sqrtf(red[0]), 1e-12f);
    out[t] = v / denom;
}

// ---------------- launch ----------------
extern "C" void kernel_launch(void* const* d_in, const int* in_sizes, int n_in,
                              void* d_out, int out_size) {
    const float* fe    = (const float*)d_in[0];
    const float* inw   = (const float*)d_in[1];
    const float* convw = (const float*)d_in[2];
    const float* convb = (const float*)d_in[3];
    const float* xpw   = (const float*)d_in[4];
    const float* dtw   = (const float*)d_in[5];
    const float* dtb   = (const float*)d_in[6];
    const float* alog  = (const float*)d_in[7];
    const float* Dp    = (const float*)d_in[8];
    const float* outw  = (const float*)d_in[9];
    float* out = (float*)d_out;

    cudaFuncSetAttribute(k_gemm1_wmma, cudaFuncAttributeMaxDynamicSharedMemorySize, G1_SMEM);

    k_prep<<<96, 256>>>(alog);                                   // 1
    k_cvt<<<((L + DI) * DM + 255) / 256, 256>>>(fe, inw);        // 2

    k_gemm1_wmma<<<dim3(DI / 128, L / 128), 256, G1_SMEM>>>();   // 3

    k_conv<<<((L / 4) * (DI / 4) + 255) / 256, 256>>>(convw, convb);  // 4

    k_gemm2<<<dim3(KS2, L / 64), 256>>>(xpw);                    // 5 (partials)
    k_xdblred<<<(L * 64 + 255) / 256, 256>>>();                  // 6
    k_gemm3<<<dim3(DI / 128, L / 128), 256>>>(dtw, dtb);         // 7 (writes g_csum)

    k_chunksuf<<<(DI + 255) / 256, 256>>>();                     // 8
    k_scan<<<dim3(DI / 128, NCHUNK), 128>>>();                   // 9
    k_zc<<<((DI + DS) * 32 + 255) / 256, 256>>>(fe, inw, xpw);   // 10
    k_hy<<<(DI + 255) / 256, 256>>>(Dp);                         // 11
    k_out1<<<DM, 256>>>(outw);                                   // 12
    k_out2<<<1, 768>>>(out);                                     // 13
}

// round 16
// speedup vs baseline: 1.0731x; 1.0731x over previous
#include <cuda_runtime.h>
#include <cuda_bf16.h>
#include <mma.h>
#include <math.h>
#include <stdint.h>

using namespace nvcuda;

#define L      4096
#define DM     768
#define DI     1536
#define DS     16
#define DTR    48
#define NCHUNK 64
#define CHUNK  (L / NCHUNK)          // 64
#define KPST   (2 * DM)              // storage: [ah|al] / [bh|bl]
#define G1_NCH 72                    // 72 chunks of 32 = 3 x 768 compute-K
#define KS2    6
#define KC2    (DI / KS2)
#define TSKIP  20.0f                 // exp(-20) ~ 2e-9: negligible vs 1e-3 gate

// ---------------- scratch ----------------
__device__ float g_xc_pre[L * DI];
__device__ float g_xc[L * DI];
__device__ float g_dt[L * DI];
__device__ float g_xdbl[L * 64];
__device__ float g_xdbl_part[KS2][L * 64];
__device__ float g_csum[NCHUNK * DI];
__device__ float g_csuf[NCHUNK * DI];
__device__ float g_hpart[NCHUNK * DI * DS];
__device__ float g_h[DI * DS];
__device__ float g_C[DS];
__device__ float g_z[DI];
__device__ float g_y[DI];
__device__ float g_outraw[DM];
__device__ int   g_nexp[DI * DS];
__device__ float g_fexp[DI * DS];
__device__ int   g_fast = 1;
__device__ __nv_bfloat16 g_feS[L * KPST];    // [ah | al]
__device__ __nv_bfloat16 g_wS[DI * KPST];    // [bh | bl]

__device__ __forceinline__ uint32_t smem_u32(const void* p) {
    uint32_t a;
    asm("{ .reg .u64 t; cvta.to.shared.u64 t, %1; cvt.u32.u64 %0, t; }" : "=r"(a) : "l"(p));
    return a;
}

// chunk t -> source K offsets: g0 ah*bh, g1 ah*bl, g2 al*bh
__device__ __forceinline__ void g1_koff(int t, int& ka, int& kb) {
    int g = t / 24, r = t - g * 24;
    int k = r * 32;
    ka = (g == 2) ? DM + k : k;
    kb = (g == 1) ? DM + k : k;
}

// ---------------- prep ----------------
__global__ void k_prep(const float* __restrict__ alog) {
    int i = blockIdx.x * blockDim.x + threadIdx.x;
    if (i >= DI * DS) return;
    int s = i % DS;
    float a = expf(alog[i]);
    int   n = (int)rintf(a);
    float f;
    bool isint = (n >= 0) && (fabsf(a - (float)n) <= 1e-4f * fmaxf(1.f, a));
    if (isint) { f = 0.f; }
    else { n = (int)floorf(a); f = a - (float)n; if (n < 0) { n = 0; f = a; } }
    g_nexp[i] = n;
    g_fexp[i] = f;
    if (!(isint && n == s + 1)) atomicAnd(&g_fast, 0);
}

// ---------------- fused split conversions (compact layout) ----------------
__global__ void k_cvt(const float* __restrict__ fe, const float* __restrict__ inw) {
    int i = blockIdx.x * blockDim.x + threadIdx.x;
    if (i < L * DM) {
        float x = fe[i];
        __nv_bfloat16 h = __float2bfloat16(x);
        __nv_bfloat16 lo = __float2bfloat16(x - __bfloat162float(h));
        int row = i / DM, col = i % DM;
        size_t base = (size_t)row * KPST;
        g_feS[base + col]      = h;
        g_feS[base + DM + col] = lo;
    } else {
        int j = i - L * DM;
        if (j >= DI * DM) return;
        float x = inw[j];
        __nv_bfloat16 h = __float2bfloat16(x);
        __nv_bfloat16 lo = __float2bfloat16(x - __bfloat162float(h));
        int row = j / DM, col = j % DM;
        size_t base = (size_t)row * KPST;
        g_wS[base + col]      = h;
        g_wS[base + DM + col] = lo;
    }
}

// ---------------- WMMA GEMM1 (R9 config), compact-layout chunk mapping ----
#define G1_BK 32
#define G1_LD 40
#define G1_STAGE_B (128 * G1_LD * 2)
#define G1_SMEM (6 * G1_STAGE_B)     // 61440

__global__ void __launch_bounds__(256)
k_gemm1_wmma() {
    extern __shared__ __align__(16) char dsm[];
    __nv_bfloat16 (*sA)[128][G1_LD] = reinterpret_cast<__nv_bfloat16 (*)[128][G1_LD]>(dsm);
    __nv_bfloat16 (*sB)[128][G1_LD] = reinterpret_cast<__nv_bfloat16 (*)[128][G1_LD]>(dsm + 3 * G1_STAGE_B);
    const int tid = threadIdx.x;
    const int wid = tid >> 5;
    const int wm = wid & 3;
    const int wn = wid >> 2;
    const int m0 = blockIdx.y * 128;
    const int n0 = blockIdx.x * 128;

    wmma::fragment<wmma::accumulator, 16, 16, 16, float> acc[2][4];
#pragma unroll
    for (int i = 0; i < 2; i++)
#pragma unroll
        for (int j = 0; j < 4; j++) wmma::fill_fragment(acc[i][j], 0.f);

    const int r0 = tid >> 2;
    const int c0 = (tid & 3) << 3;

#define G1_ISSUE(st, tt)                                                              \
    do {                                                                              \
        int _ka, _kb; g1_koff((tt), _ka, _kb);                                        \
        _Pragma("unroll")                                                             \
        for (int h = 0; h < 2; h++) {                                                 \
            int r = r0 + h * 64;                                                      \
            uint32_t sa = smem_u32(&sA[st][r][c0]);                                   \
            uint32_t sb = smem_u32(&sB[st][r][c0]);                                   \
            const void* ga = &g_feS[(size_t)(m0 + r) * KPST + _ka + c0];              \
            const void* gb = &g_wS[(size_t)(n0 + r) * KPST + _kb + c0];               \
            asm volatile("cp.async.cg.shared.global [%0], [%1], 16;" :: "r"(sa), "l"(ga)); \
            asm volatile("cp.async.cg.shared.global [%0], [%1], 16;" :: "r"(sb), "l"(gb)); \
        }                                                                             \
        asm volatile("cp.async.commit_group;");                                       \
    } while (0)

    G1_ISSUE(0, 0);
    G1_ISSUE(1, 1);
    for (int t = 0; t < G1_NCH; t++) {
        if (t + 1 < G1_NCH) asm volatile("cp.async.wait_group 1;");
        else                asm volatile("cp.async.wait_group 0;");
        __syncthreads();
        if (t + 2 < G1_NCH) G1_ISSUE((t + 2) % 3, t + 2);
        const int st = t % 3;
#pragma unroll
        for (int kk = 0; kk < G1_BK; kk += 16) {
            wmma::fragment<wmma::matrix_a, 16, 16, 16, __nv_bfloat16, wmma::row_major> fa[2];
            wmma::fragment<wmma::matrix_b, 16, 16, 16, __nv_bfloat16, wmma::col_major> fb[4];
#pragma unroll
            for (int i = 0; i < 2; i++)
                wmma::load_matrix_sync(fa[i], &sA[st][wm * 32 + i * 16][kk], G1_LD);
#pragma unroll
            for (int j = 0; j < 4; j++)
                wmma::load_matrix_sync(fb[j], &sB[st][wn * 64 + j * 16][kk], G1_LD);
#pragma unroll
            for (int i = 0; i < 2; i++)
#pragma unroll
                for (int j = 0; j < 4; j++)
                    wmma::mma_sync(acc[i][j], fa[i], fb[j], acc[i][j]);
        }
    }
    __syncthreads();
#pragma unroll
    for (int i = 0; i < 2; i++)
#pragma unroll
        for (int j = 0; j < 4; j++)
            wmma::store_matrix_sync(
                &g_xc_pre[(size_t)(m0 + wm * 32 + i * 16) * DI + n0 + wn * 64 + j * 16],
                acc[i][j], DI, wmma::mem_row_major);
}

// ------- SIMT SGEMM body (NT); EPI: 0=store, 1=softplus+chunksum ----------
template<int BM, int BN, int BK, int TM, int TN, int EPI>
__device__ __forceinline__ void sgemm_nt_body(
        int kbeg, int kend,
        const float* __restrict__ A, int lda,
        const float* __restrict__ B, int ldb,
        float* __restrict__ C, int ldc,
        const float* __restrict__ bias,
        int m0, int n0) {
    constexpr int THREADS = (BM / TM) * (BN / TN);
    __shared__ float As[BK][BM];
    __shared__ float Bs[BK][BN];
    const int tid = threadIdx.x;
    const int tx = tid % (BN / TN);
    const int ty = tid / (BN / TN);

    float acc[TM][TN];
#pragma unroll
    for (int i = 0; i < TM; i++)
#pragma unroll
        for (int j = 0; j < TN; j++) acc[i][j] = 0.f;

    for (int k0 = kbeg; k0 < kend; k0 += BK) {
#pragma unroll
        for (int i = tid; i < BM * (BK / 4); i += THREADS) {
            int r = i / (BK / 4), c = (i % (BK / 4)) * 4;
            float4 v = *reinterpret_cast<const float4*>(A + (size_t)(m0 + r) * lda + k0 + c);
            As[c + 0][r] = v.x; As[c + 1][r] = v.y; As[c + 2][r] = v.z; As[c + 3][r] = v.w;
        }
#pragma unroll
        for (int i = tid; i < BN * (BK / 4); i += THREADS) {
            int r = i / (BK / 4), c = (i % (BK / 4)) * 4;
            float4 v = *reinterpret_cast<const float4*>(B + (size_t)(n0 + r) * ldb + k0 + c);
            Bs[c + 0][r] = v.x; Bs[c + 1][r] = v.y; Bs[c + 2][r] = v.z; Bs[c + 3][r] = v.w;
        }
        __syncthreads();
#pragma unroll
        for (int kk = 0; kk < BK; kk++) {
            float ra[TM], rb[TN];
#pragma unroll
            for (int i = 0; i < TM; i += 4) {
                float4 v = *reinterpret_cast<const float4*>(&As[kk][ty * TM + i]);
                ra[i] = v.x; ra[i + 1] = v.y; ra[i + 2] = v.z; ra[i + 3] = v.w;
            }
#pragma unroll
            for (int j = 0; j < TN; j += 4) {
                float4 v = *reinterpret_cast<const float4*>(&Bs[kk][tx * TN + j]);
                rb[j] = v.x; rb[j + 1] = v.y; rb[j + 2] = v.z; rb[j + 3] = v.w;
            }
#pragma unroll
            for (int i = 0; i < TM; i++)
#pragma unroll
                for (int j = 0; j < TN; j++) acc[i][j] = fmaf(ra[i], rb[j], acc[i][j]);
        }
        __syncthreads();
    }

    if (EPI == 0) {
#pragma unroll
        for (int i = 0; i < TM; i++) {
#pragma unroll
            for (int j = 0; j < TN; j += 4) {
                float4 v = make_float4(acc[i][j], acc[i][j + 1], acc[i][j + 2], acc[i][j + 3]);
                *reinterpret_cast<float4*>(C + (size_t)(m0 + ty * TM + i) * ldc + n0 + tx * TN + j) = v;
            }
        }
    } else {
        __shared__ float s_cs[16][128];
        float colsum[TN];
#pragma unroll
        for (int j = 0; j < TN; j++) colsum[j] = 0.f;
#pragma unroll
        for (int i = 0; i < TM; i++) {
#pragma unroll
            for (int j = 0; j < TN; j += 4) {
                float vv[4];
                int col = n0 + tx * TN + j;
#pragma unroll
                for (int t = 0; t < 4; t++) {
                    float x = acc[i][j + t] + bias[col + t];
                    vv[t] = fmaxf(x, 0.f) + log1pf(__expf(-fabsf(x)));
                    colsum[j + t] += vv[t];
                }
                float4 v = make_float4(vv[0], vv[1], vv[2], vv[3]);
                *reinterpret_cast<float4*>(C + (size_t)(m0 + ty * TM + i) * ldc + n0 + tx * TN + j) = v;
            }
        }
#pragma unroll
        for (int j = 0; j < TN; j++) s_cs[ty][tx * TN + j] = colsum[j];
        __syncthreads();
        int h = tid >> 7, col = tid & 127;
        float s = 0.f;
#pragma unroll
        for (int q = 0; q < 8; q++) s += s_cs[h * 8 + q][col];
        g_csum[(size_t)(blockIdx.y * 2 + h) * DI + n0 + col] = s;
    }
}

__global__ void __launch_bounds__(256)
k_gemm2(const float* __restrict__ xpw) {
    int ck = blockIdx.x;
    sgemm_nt_body<64, 64, 16, 4, 4, 0>(
        ck * KC2, (ck + 1) * KC2,
        g_xc, DI, xpw, DI, g_xdbl_part[ck], 64, nullptr,
        blockIdx.y * 64, 0);
}

__global__ void k_xdblred() {
    int i = blockIdx.x * blockDim.x + threadIdx.x;
    if (i >= L * 64) return;
    float s = 0.f;
#pragma unroll
    for (int c = 0; c < KS2; c++) s += g_xdbl_part[c][i];
    g_xdbl[i] = s;
}

__global__ void __launch_bounds__(256)
k_gemm3(const float* __restrict__ dtw, const float* __restrict__ dtb) {
    sgemm_nt_body<128, 128, 16, 8, 8, 1>(
        0, DTR, g_xdbl, 64, dtw, DTR, g_dt, DI, dtb,
        blockIdx.y * 128, blockIdx.x * 128);
}

// ---------------- depthwise causal conv(4) + bias + silu (4d x 4l tiles) ---
__global__ void k_conv(const float* __restrict__ w, const float* __restrict__ b) {
    int idx = blockIdx.x * blockDim.x + threadIdx.x;
    if (idx >= (L / 4) * (DI / 4)) return;
    int dq = idx % (DI / 4);
    int g  = idx / (DI / 4);
    int d0 = dq * 4, l0 = g * 4;
    const float4* wp = reinterpret_cast<const float4*>(w) + d0;
    float4 w0 = wp[0], w1 = wp[1], w2 = wp[2], w3 = wp[3];
    float4 bb = *reinterpret_cast<const float4*>(b + d0);
    float4 x[7];
#pragma unroll
    for (int t = 0; t < 7; t++) {
        int l = l0 - 3 + t;
        x[t] = (l >= 0) ? *reinterpret_cast<const float4*>(&g_xc_pre[(size_t)l * DI + d0])
                        : make_float4(0.f, 0.f, 0.f, 0.f);
    }
#pragma unroll
    for (int t = 0; t < 4; t++) {
        float4 s;
        s.x = bb.x; s.y = bb.y; s.z = bb.z; s.w = bb.w;
        s.x = fmaf(w0.x, x[t].x, s.x); s.x = fmaf(w0.y, x[t+1].x, s.x); s.x = fmaf(w0.z, x[t+2].x, s.x); s.x = fmaf(w0.w, x[t+3].x, s.x);
        s.y = fmaf(w1.x, x[t].y, s.y); s.y = fmaf(w1.y, x[t+1].y, s.y); s.y = fmaf(w1.z, x[t+2].y, s.y); s.y = fmaf(w1.w, x[t+3].y, s.y);
        s.z = fmaf(w2.x, x[t].z, s.z); s.z = fmaf(w2.y, x[t+1].z, s.z); s.z = fmaf(w2.z, x[t+2].z, s.z); s.z = fmaf(w2.w, x[t+3].z, s.z);
        s.w = fmaf(w3.x, x[t].w, s.w); s.w = fmaf(w3.y, x[t+1].w, s.w); s.w = fmaf(w3.z, x[t+2].w, s.w); s.w = fmaf(w3.w, x[t+3].w, s.w);
        s.x = s.x / (1.f + __expf(-s.x));
        s.y = s.y / (1.f + __expf(-s.y));
        s.z = s.z / (1.f + __expf(-s.z));
        s.w = s.w / (1.f + __expf(-s.w));
        *reinterpret_cast<float4*>(&g_xc[(size_t)(l0 + t) * DI + d0]) = s;
    }
}

// ---------------- suffix over chunk sums ----------------
__global__ void k_chunksuf() {
    int d = blockIdx.x * blockDim.x + threadIdx.x;
    if (d >= DI) return;
    double t = 0.0;
    for (int c = NCHUNK - 1; c >= 0; --c) {
        g_csuf[c * DI + d] = (float)t;
        t += (double)g_csum[c * DI + d];
    }
}

// -------- parallel closed-form scan (B smem-staged, decay early-exit) ------
__global__ void k_scan() {
    __shared__ float sB[16][16];
    int tid = threadIdx.x;
    int d = blockIdx.x * 128 + tid;
    int c = blockIdx.y;
    float t = g_csuf[c * DI + d];
    float acc[DS];
#pragma unroll
    for (int s = 0; s < DS; s++) acc[s] = 0.f;
    const int l0 = c * CHUNK;
    const bool fast = (g_fast != 0);
    const bool sk = (t > TSKIP);              // whole chunk decays to zero

    if (__syncthreads_and(sk)) {
#pragma unroll
        for (int s = 0; s < DS; s++)
            g_hpart[(size_t)c * DI * DS + d * DS + s] = 0.f;
        return;
    }

    if (fast) {
        const bool wskip = __all_sync(0xFFFFFFFFu, sk);
        for (int lt = CHUNK - 16; lt >= 0; lt -= 16) {
            __syncthreads();
            {
                int i = tid * 2;
                int ll = i >> 4, ss = i & 15;
                float2 v = *reinterpret_cast<const float2*>(
                    &g_xdbl[(size_t)(l0 + lt + ll) * 64 + DTR + ss]);
                sB[ll][ss] = v.x; sB[ll][ss + 1] = v.y;
            }
            __syncthreads();
            if (!wskip) {
#pragma unroll
                for (int j = 15; j >= 0; --j) {
                    int l = l0 + lt + j;
                    float dt = g_dt[(size_t)l * DI + d];
                    float w  = dt * g_xc[(size_t)l * DI + d];
                    float E = __expf(-t);
                    float p = 1.f;
#pragma unroll
                    for (int s = 0; s < DS; s++) { p *= E; acc[s] = fmaf(w * p, sB[j][s], acc[s]); }
                    t += dt;
                }
            }
        }
    } else {
        if (!sk) {
            int nn[DS]; float ff[DS];
#pragma unroll
            for (int s = 0; s < DS; s++) { nn[s] = g_nexp[d * DS + s]; ff[s] = g_fexp[d * DS + s]; }
            for (int l = l0 + CHUNK - 1; l >= l0; --l) {
                const float* brow = g_xdbl + (size_t)l * 64 + DTR;
                float dt = g_dt[(size_t)l * DI + d];
                float w  = dt * g_xc[(size_t)l * DI + d];
                float E = __expf(-t);
#pragma unroll
                for (int s = 0; s < DS; s++) {
                    float p = 1.f, base = E;
                    int m = nn[s];
                    while (m) { if (m & 1) p *= base; base *= base; m >>= 1; }
                    if (ff[s] != 0.f) p *= __expf(-t * ff[s]);
                    acc[s] = fmaf(w * p, brow[s], acc[s]);
                }
                t += dt;
            }
        }
    }
#pragma unroll
    for (int s = 0; s < DS; s++)
        g_hpart[(size_t)c * DI * DS + d * DS + s] = acc[s];
}

// ---------------- h reduction (wide) ----------------
__global__ void k_hred() {
    int i = blockIdx.x * blockDim.x + threadIdx.x;
    if (i >= DI * DS) return;
    float s = 0.f;
#pragma unroll
    for (int c = 0; c < NCHUNK; c++) s += g_hpart[(size_t)c * DI * DS + i];
    g_h[i] = s;
}

// ---------------- fused last-step GEMVs (z and C) ----------------
__global__ void k_zc(const float* __restrict__ fe, const float* __restrict__ inw,
                     const float* __restrict__ xpw) {
    int gw = (blockIdx.x * blockDim.x + threadIdx.x) / 32;
    int lane = threadIdx.x % 32;
    if (gw < DI) {
        const float* a = fe + (size_t)(L - 1) * DM;
        const float* w = inw + (size_t)(DI + gw) * DM;
        float s = 0.f;
        for (int m = lane; m < DM; m += 32) s = fmaf(a[m], w[m], s);
#pragma unroll
        for (int o = 16; o; o >>= 1) s += __shfl_xor_sync(0xFFFFFFFFu, s, o);
        if (lane == 0) g_z[gw] = s;
    } else if (gw < DI + DS) {
        int sidx = gw - DI;
        const float* a = g_xc + (size_t)(L - 1) * DI;
        const float* w = xpw + (size_t)(DTR + DS + sidx) * DI;
        float acc = 0.f;
        for (int d = lane; d < DI; d += 32) acc = fmaf(a[d], w[d], acc);
#pragma unroll
        for (int o = 16; o; o >>= 1) acc += __shfl_xor_sync(0xFFFFFFFFu, acc, o);
        if (lane == 0) g_C[sidx] = acc;
    }
}

__global__ void k_y(const float* __restrict__ Dp) {
    int d = blockIdx.x * blockDim.x + threadIdx.x;
    if (d >= DI) return;
    float s = 0.f;
#pragma unroll
    for (int j = 0; j < DS; j++) s = fmaf(g_h[d * DS + j], g_C[j], s);
    float y = s + g_xc[(size_t)(L - 1) * DI + d] * Dp[d];
    float z = g_z[d];
    y *= z / (1.f + __expf(-z));
    g_y[d] = y;
}

__global__ void k_out1(const float* __restrict__ outw) {
    int e = blockIdx.x;
    const float* w = outw + (size_t)e * DI;
    float s = 0.f;
    for (int d = threadIdx.x; d < DI; d += 256) s = fmaf(g_y[d], w[d], s);
    __shared__ float red[256];
    red[threadIdx.x] = s;
    __syncthreads();
    for (int o = 128; o >= 1; o >>= 1) {
        if (threadIdx.x < o) red[threadIdx.x] += red[threadIdx.x + o];
        __syncthreads();
    }
    if (threadIdx.x == 0) g_outraw[e] = red[0];
}

__global__ void k_out2(float* __restrict__ out) {
    int t = threadIdx.x;
    float v = g_outraw[t];
    __shared__ float red[768];
    red[t] = v * v;
    __syncthreads();
    if (t < 256) red[t] += red[t + 256] + red[t + 512];
    __syncthreads();
    for (int o = 128; o >= 1; o >>= 1) {
        if (t < o) red[t] += red[t + o];
        __syncthreads();
    }
    float denom = fmaxf(sqrtf(red[0]), 1e-12f);
    out[t] = v / denom;
}

// ---------------- launch ----------------
extern "C" void kernel_launch(void* const* d_in, const int* in_sizes, int n_in,
                              void* d_out, int out_size) {
    const float* fe    = (const float*)d_in[0];
    const float* inw   = (const float*)d_in[1];
    const float* convw = (const float*)d_in[2];
    const float* convb = (const float*)d_in[3];
    const float* xpw   = (const float*)d_in[4];
    const float* dtw   = (const float*)d_in[5];
    const float* dtb   = (const float*)d_in[6];
    const float* alog  = (const float*)d_in[7];
    const float* Dp    = (const float*)d_in[8];
    const float* outw  = (const float*)d_in[9];
    float* out = (float*)d_out;

    cudaFuncSetAttribute(k_gemm1_wmma, cudaFuncAttributeMaxDynamicSharedMemorySize, G1_SMEM);

    k_prep<<<96, 256>>>(alog);                                   // 1
    k_cvt<<<((L + DI) * DM + 255) / 256, 256>>>(fe, inw);        // 2

    k_gemm1_wmma<<<dim3(DI / 128, L / 128), 256, G1_SMEM>>>();   // 3

    k_conv<<<((L / 4) * (DI / 4) + 255) / 256, 256>>>(convw, convb);  // 4

    k_gemm2<<<dim3(KS2, L / 64), 256>>>(xpw);                    // 5 (partials)
    k_xdblred<<<(L * 64 + 255) / 256, 256>>>();                  // 6
    k_gemm3<<<dim3(DI / 128, L / 128), 256>>>(dtw, dtb);         // 7 (writes g_csum)

    k_chunksuf<<<(DI + 255) / 256, 256>>>();                     // 8
    k_scan<<<dim3(DI / 128, NCHUNK), 128>>>();                   // 9
    k_hred<<<(DI * DS + 255) / 256, 256>>>();                    // 10
    k_zc<<<((DI + DS) * 32 + 255) / 256, 256>>>(fe, inw, xpw);   // 11
    k_y<<<(DI + 255) / 256, 256>>>(Dp);                          // 12
    k_out1<<<DM, 256>>>(outw);                                   // 13
    k_out2<<<1, 768>>>(out);                                     // 14
}